// round 4
// baseline (speedup 1.0000x reference)
#include <cuda_runtime.h>
#include <math.h>

#define NPATCH 196
#define BLOCK  256   // 8 warps: 196 active in phase 1, 250 active in phase 2

__global__ __launch_bounds__(BLOCK)
void quanv_fused_kernel(const float* __restrict__ x,
                        const float* __restrict__ emb_W,
                        const float* __restrict__ emb_b,
                        const float* __restrict__ q_params,
                        const float* __restrict__ lin_W,
                        const float* __restrict__ lin_b,
                        float* __restrict__ out)
{
    __shared__ float4 sfeats[NPATCH];     // 4 features per patch
    __shared__ float  part[10][26];       // 25 partials per channel (+pad)
    __shared__ float  slog[10];

    const int b   = blockIdx.x;
    const int tid = threadIdx.x;

    // ---- phase 1: per-patch features via closed-form circuit ----
    if (tid < NPATCH) {
        // uniform circuit constants (broadcast loads + MUFU)
        const float Kc0 = __cosf(q_params[0]);           // cos q0
        const float Kq1 = q_params[1];                   // q1
        float s4, c4;
        __sincosf(q_params[4], &s4, &c4);                // sin/cos q4
        const float Ks4 = s4 * __cosf(q_params[2]);      // sin q4 * cos q2
        const float Kc3 = __cosf(q_params[3]);           // cos q3

        // direct coalesced pixel loads: two float2 per thread
        const int pr = tid / 14, pc = tid % 14;
        const float2 top = *(const float2*)(x + b * 784 + (2 * pr) * 28 + 2 * pc);
        const float2 bot = *(const float2*)(x + b * 784 + (2 * pr + 1) * 28 + 2 * pc);

        // angles = patch @ emb_W^T + emb_b
        float ang[4];
#pragma unroll
        for (int j = 0; j < 4; j++) {
            const float4 w = __ldg((const float4*)(emb_W + 4 * j));
            ang[j] = fmaf(top.x, w.x, fmaf(top.y, w.y,
                     fmaf(bot.x, w.z, fmaf(bot.y, w.w, emb_b[j]))));
        }

        // closed-form <Z_w>
        const float ca0  = __cosf(ang[0]);
        const float ca1q = __cosf(ang[1] + Kq1);
        float sa2, ca2, sa3, ca3;
        __sincosf(ang[2], &sa2, &ca2);
        __sincosf(ang[3], &sa3, &ca3);

        const float e0 = Kc0 * ca0;
        const float e1 = e0 * ca1q;
        const float e2 = e1 * fmaf(c4, ca2, -Ks4 * sa2 * sa3);
        const float e3 = ca2 * (Kc3 * ca3);

        sfeats[tid] = make_float4(e0, e1, e2, e3);
    }
    __syncthreads();

    // ---- phase 2: 10x784 GEMV from smem ----
    if (tid < 250) {
        const int c = tid / 25, k = tid % 25;
        const float4* lw4 = (const float4*)lin_W;   // lin_W[c*784 + 4*j]
        float s = 0.f;
        for (int j = k; j < NPATCH; j += 25) {
            const float4 f = sfeats[j];
            const float4 w = __ldg(&lw4[c * NPATCH + j]);
            s = fmaf(f.x, w.x, fmaf(f.y, w.y, fmaf(f.z, w.z, fmaf(f.w, w.w, s))));
        }
        part[c][k] = s;
    }
    __syncthreads();

    if (tid < 10) {
        float s = lin_b[tid];
#pragma unroll
        for (int k = 0; k < 25; k++) s += part[tid][k];
        slog[tid] = s;
    }
    __syncthreads();

    // ---- log_softmax (10 threads, redundant scan) ----
    if (tid < 10) {
        float mx = slog[0];
#pragma unroll
        for (int c = 1; c < 10; c++) mx = fmaxf(mx, slog[c]);
        float se = 0.f;
#pragma unroll
        for (int c = 0; c < 10; c++) se += __expf(slog[c] - mx);
        const float lse = mx + __logf(se);
        out[b * 10 + tid] = slog[tid] - lse;
    }
}

extern "C" void kernel_launch(void* const* d_in, const int* in_sizes, int n_in,
                              void* d_out, int out_size)
{
    const float* x        = (const float*)d_in[0];
    const float* emb_W    = (const float*)d_in[1];
    const float* emb_b    = (const float*)d_in[2];
    const float* q_params = (const float*)d_in[3];
    const float* lin_W    = (const float*)d_in[4];
    const float* lin_b    = (const float*)d_in[5];
    float* out = (float*)d_out;

    const int B = in_sizes[0] / 784;
    quanv_fused_kernel<<<B, BLOCK>>>(x, emb_W, emb_b, q_params, lin_W, lin_b, out);
}

// round 5
// speedup vs baseline: 2.0923x; 2.0923x over previous
#include <cuda_runtime.h>
#include <math.h>

#define NPATCH 196
#define WPB    4      // images (warps) per block
#define BLOCK  (WPB * 32)

__global__ __launch_bounds__(BLOCK)
void quanv_fused_kernel(const float* __restrict__ x,
                        const float* __restrict__ emb_W,
                        const float* __restrict__ emb_b,
                        const float* __restrict__ q_params,
                        const float* __restrict__ lin_W,
                        const float* __restrict__ lin_b,
                        float* __restrict__ out,
                        int B)
{
    const int warp = threadIdx.x >> 5;
    const int lane = threadIdx.x & 31;
    const int b    = blockIdx.x * WPB + warp;
    if (b >= B) return;

    // ---- uniform circuit constants (broadcast loads + MUFU) ----
    const float Kc0 = __cosf(q_params[0]);           // cos q0
    const float Kq1 = q_params[1];                   // q1
    float s4, c4;
    __sincosf(q_params[4], &s4, &c4);                // sin/cos q4
    const float Ks4 = s4 * __cosf(q_params[2]);      // sin q4 * cos q2
    const float Kc3 = __cosf(q_params[3]);           // cos q3

    const float4 W0 = __ldg((const float4*)(emb_W + 0));
    const float4 W1 = __ldg((const float4*)(emb_W + 4));
    const float4 W2 = __ldg((const float4*)(emb_W + 8));
    const float4 W3 = __ldg((const float4*)(emb_W + 12));
    const float4 eb = __ldg((const float4*)emb_b);

    const float*  xb  = x + b * 784;
    const float4* lw4 = (const float4*)lin_W;   // lin_W[c*784 + 4*p] == lw4[c*196 + p]

    float acc[10];
#pragma unroll
    for (int c = 0; c < 10; c++) acc[c] = 0.f;

    // lane handles patches p = lane, lane+32, ... (6 full rounds + tail for lanes 0..3)
#pragma unroll
    for (int k = 0; k < 7; k++) {
        const int p = lane + 32 * k;
        if (k == 6 && p >= NPATCH) break;          // only lanes 0..3 do round 7

        const int pr = p / 14, pc = p % 14;
        const float2 top = *(const float2*)(xb + (2 * pr) * 28 + 2 * pc);
        const float2 bot = *(const float2*)(xb + (2 * pr + 1) * 28 + 2 * pc);

        const float a0 = fmaf(top.x, W0.x, fmaf(top.y, W0.y, fmaf(bot.x, W0.z, fmaf(bot.y, W0.w, eb.x))));
        const float a1 = fmaf(top.x, W1.x, fmaf(top.y, W1.y, fmaf(bot.x, W1.z, fmaf(bot.y, W1.w, eb.y))));
        const float a2 = fmaf(top.x, W2.x, fmaf(top.y, W2.y, fmaf(bot.x, W2.z, fmaf(bot.y, W2.w, eb.z))));
        const float a3 = fmaf(top.x, W3.x, fmaf(top.y, W3.y, fmaf(bot.x, W3.z, fmaf(bot.y, W3.w, eb.w))));

        // closed-form <Z_w> of the 4-qubit circuit
        const float ca0  = __cosf(a0);
        const float ca1q = __cosf(a1 + Kq1);
        float sa2, ca2, sa3, ca3;
        __sincosf(a2, &sa2, &ca2);
        __sincosf(a3, &sa3, &ca3);

        const float e0 = Kc0 * ca0;
        const float e1 = e0 * ca1q;
        const float e2 = e1 * fmaf(c4, ca2, -Ks4 * sa2 * sa3);
        const float e3 = ca2 * (Kc3 * ca3);

        // accumulate partial logits (coalesced 512B per channel per round)
#pragma unroll
        for (int c = 0; c < 10; c++) {
            const float4 w = __ldg(&lw4[c * NPATCH + p]);
            acc[c] = fmaf(e0, w.x, fmaf(e1, w.y, fmaf(e2, w.z, fmaf(e3, w.w, acc[c]))));
        }
    }

    // ---- xor-butterfly: every lane ends with the full 10 logit sums ----
#pragma unroll
    for (int off = 16; off > 0; off >>= 1)
#pragma unroll
        for (int c = 0; c < 10; c++)
            acc[c] += __shfl_xor_sync(0xffffffffu, acc[c], off);

    // ---- log_softmax, lanes 0..9 write coalesced ----
    if (lane < 10) {
        float lg[10];
#pragma unroll
        for (int c = 0; c < 10; c++) lg[c] = acc[c] + __ldg(&lin_b[c]);

        float mx = lg[0];
#pragma unroll
        for (int c = 1; c < 10; c++) mx = fmaxf(mx, lg[c]);
        float se = 0.f;
#pragma unroll
        for (int c = 0; c < 10; c++) se += __expf(lg[c] - mx);
        const float lse = mx + __logf(se);

        float v = lg[0];
#pragma unroll
        for (int c = 1; c < 10; c++) if (lane == c) v = lg[c];
        out[b * 10 + lane] = v - lse;
    }
}

extern "C" void kernel_launch(void* const* d_in, const int* in_sizes, int n_in,
                              void* d_out, int out_size)
{
    const float* x        = (const float*)d_in[0];
    const float* emb_W    = (const float*)d_in[1];
    const float* emb_b    = (const float*)d_in[2];
    const float* q_params = (const float*)d_in[3];
    const float* lin_W    = (const float*)d_in[4];
    const float* lin_b    = (const float*)d_in[5];
    float* out = (float*)d_out;

    const int B = in_sizes[0] / 784;
    const int grid = (B + WPB - 1) / WPB;
    quanv_fused_kernel<<<grid, BLOCK>>>(x, emb_W, emb_b, q_params, lin_W, lin_b, out, B);
}